// round 2
// baseline (speedup 1.0000x reference)
#include <cuda_runtime.h>

#define ND 50000
#define NP 50000
#define EE 600000
#define DIN 128
#define DH  128
#define DO  64

// ---------------- scratch layout (single __device__ global) ----------------
// zeroed region first:
constexpr size_t AGG_D    = 0;                                  // [ND*DH] layer1 ddi agg -> becomes h_d
constexpr size_t AGG_P1   = AGG_D   + (size_t)ND * DH;          // [NP*DH] layer1 dpi agg -> becomes h_p
constexpr size_t AGG_P2   = AGG_P1  + (size_t)NP * DH;          // [NP*DH] layer1 ppi agg
constexpr size_t OAGG_PPI = AGG_P2  + (size_t)NP * DH;          // [NP*DO] layer2 ppi agg
constexpr size_t DEG_DDI  = OAGG_PPI + (size_t)NP * DO;         // [ND]
constexpr size_t DEG_DPI  = DEG_DDI + ND;                       // [NP]
constexpr size_t DEG_PPI  = DEG_DPI + NP;                       // [NP]
constexpr size_t ZTOTAL   = DEG_PPI + NP;                       // end of zeroed region
// non-zeroed scratch:
constexpr size_t T1_DDI   = ZTOTAL;                             // [ND*DH]
constexpr size_t T1_DPI   = T1_DDI + (size_t)ND * DH;
constexpr size_t T1_PPI   = T1_DPI + (size_t)ND * DH;
constexpr size_t T2_DDI   = T1_PPI + (size_t)NP * DH;           // [ND*DO]
constexpr size_t T2_DPI   = T2_DDI + (size_t)ND * DO;
constexpr size_t T2_PPI   = T2_DPI + (size_t)ND * DO;
constexpr size_t TOTAL    = T2_PPI + (size_t)NP * DO;

__device__ float g_buf[TOTAL];

// ---------------- kernels ----------------

__global__ void zero_kernel(float4* __restrict__ p, int n4) {
    int i = blockIdx.x * blockDim.x + threadIdx.x;
    int stride = gridDim.x * blockDim.x;
    for (; i < n4; i += stride) p[i] = make_float4(0.f, 0.f, 0.f, 0.f);
}

__global__ void degree_kernel(const int* __restrict__ dst_ddi,
                              const int* __restrict__ dst_dpi,
                              const int* __restrict__ dst_ppi,
                              float* __restrict__ deg_ddi,
                              float* __restrict__ deg_dpi,
                              float* __restrict__ deg_ppi) {
    int i = blockIdx.x * blockDim.x + threadIdx.x;
    if (i < EE) {
        atomicAdd(&deg_ddi[dst_ddi[i]], 1.0f);
        atomicAdd(&deg_dpi[dst_dpi[i]], 1.0f);
        atomicAdd(&deg_ppi[dst_ppi[i]], 1.0f);
    }
}

// C[M x N] = A[M x 128] @ W[128 x N], fp32. BM=64, BK=32, 256 threads.
template <int N>
__global__ void __launch_bounds__(256) gemm_kernel(const float* __restrict__ A,
                                                   const float* __restrict__ W,
                                                   float* __restrict__ C, int M) {
    constexpr int BM = 64;
    constexpr int K  = 128;
    constexpr int BK = 32;
    constexpr int NTX = N / 4;        // threads along N (each does float4)
    constexpr int NTY = 256 / NTX;    // threads along M
    constexpr int TM  = BM / NTY;     // rows per thread

    __shared__ float As[BM * K];      // 32 KB
    __shared__ float Ws[BK * N];      // 16 KB (N=128) / 8 KB (N=64)

    int tid = threadIdx.x;
    int m0  = blockIdx.x * BM;
    int rows = M - m0; if (rows > BM) rows = BM;

    const float4* A4 = (const float4*)(A + (size_t)m0 * K);
    for (int i = tid; i < rows * (K / 4); i += 256)
        ((float4*)As)[i] = A4[i];

    int tx = tid % NTX;
    int ty = tid / NTX;
    float acc[TM][4];
#pragma unroll
    for (int r = 0; r < TM; r++) { acc[r][0]=0.f; acc[r][1]=0.f; acc[r][2]=0.f; acc[r][3]=0.f; }

    for (int kk = 0; kk < K; kk += BK) {
        __syncthreads();
        const float4* W4 = (const float4*)(W + (size_t)kk * N);
        for (int i = tid; i < BK * N / 4; i += 256)
            ((float4*)Ws)[i] = W4[i];
        __syncthreads();
#pragma unroll
        for (int k = 0; k < BK; k++) {
            float4 w = ((const float4*)Ws)[k * (N / 4) + tx];
#pragma unroll
            for (int r = 0; r < TM; r++) {
                float a = As[(ty * TM + r) * K + kk + k];
                acc[r][0] += a * w.x;
                acc[r][1] += a * w.y;
                acc[r][2] += a * w.z;
                acc[r][3] += a * w.w;
            }
        }
    }

#pragma unroll
    for (int r = 0; r < TM; r++) {
        int m = m0 + ty * TM + r;
        if (m < M) {
            float4 o = make_float4(acc[r][0], acc[r][1], acc[r][2], acc[r][3]);
            ((float4*)(C + (size_t)m * N))[tx] = o;
        }
    }
}

// one warp per edge; 128 floats = float4 per lane
__global__ void scatter128_kernel(const float* __restrict__ t,
                                  const int* __restrict__ src,
                                  const int* __restrict__ dst,
                                  float* __restrict__ agg) {
    int gw   = (blockIdx.x * blockDim.x + threadIdx.x) >> 5;
    int lane = threadIdx.x & 31;
    if (gw >= EE) return;
    int s = __ldg(&src[gw]);
    int d = __ldg(&dst[gw]);
    float4 v = ((const float4*)(t + (size_t)s * 128))[lane];
    float* o = agg + (size_t)d * 128 + lane * 4;
    atomicAdd(o + 0, v.x);
    atomicAdd(o + 1, v.y);
    atomicAdd(o + 2, v.z);
    atomicAdd(o + 3, v.w);
}

// one warp per edge; 64 floats = float2 per lane
__global__ void scatter64_kernel(const float* __restrict__ t,
                                 const int* __restrict__ src,
                                 const int* __restrict__ dst,
                                 float* __restrict__ agg) {
    int gw   = (blockIdx.x * blockDim.x + threadIdx.x) >> 5;
    int lane = threadIdx.x & 31;
    if (gw >= EE) return;
    int s = __ldg(&src[gw]);
    int d = __ldg(&dst[gw]);
    float2 v = ((const float2*)(t + (size_t)s * 64))[lane];
    float* o = agg + (size_t)d * 64 + lane * 2;
    atomicAdd(o + 0, v.x);
    atomicAdd(o + 1, v.y);
}

// h_d = agg_d / max(deg,1) + b1   (in place; 128-dim rows, float4 granularity)
__global__ void fin1_drug_kernel(float* __restrict__ agg,
                                 const float* __restrict__ deg,
                                 const float* __restrict__ b) {
    int i = blockIdx.x * blockDim.x + threadIdx.x;   // over ND*32 float4s
    if (i >= ND * 32) return;
    int row = i >> 5;
    int c4  = i & 31;
    float inv = 1.0f / fmaxf(deg[row], 1.0f);
    float4 v = ((float4*)agg)[i];
    float4 bb = ((const float4*)b)[c4];
    v.x = v.x * inv + bb.x;
    v.y = v.y * inv + bb.y;
    v.z = v.z * inv + bb.z;
    v.w = v.w * inv + bb.w;
    ((float4*)agg)[i] = v;
}

// h_p = agg1/deg_dpi + b_dpi + agg2/deg_ppi + b_ppi  (written into agg1)
__global__ void fin1_prot_kernel(float* __restrict__ agg1,
                                 const float* __restrict__ agg2,
                                 const float* __restrict__ deg1,
                                 const float* __restrict__ deg2,
                                 const float* __restrict__ b1,
                                 const float* __restrict__ b2) {
    int i = blockIdx.x * blockDim.x + threadIdx.x;   // over NP*32 float4s
    if (i >= NP * 32) return;
    int row = i >> 5;
    int c4  = i & 31;
    float inv1 = 1.0f / fmaxf(deg1[row], 1.0f);
    float inv2 = 1.0f / fmaxf(deg2[row], 1.0f);
    float4 v1 = ((float4*)agg1)[i];
    float4 v2 = ((const float4*)agg2)[i];
    float4 bb1 = ((const float4*)b1)[c4];
    float4 bb2 = ((const float4*)b2)[c4];
    v1.x = v1.x * inv1 + bb1.x + v2.x * inv2 + bb2.x;
    v1.y = v1.y * inv1 + bb1.y + v2.y * inv2 + bb2.y;
    v1.z = v1.z * inv1 + bb1.z + v2.z * inv2 + bb2.z;
    v1.w = v1.w * inv1 + bb1.w + v2.w * inv2 + bb2.w;
    ((float4*)agg1)[i] = v1;
}

// o_d = out/deg_ddi + b2_ddi (in place on d_out, 64-dim rows)
__global__ void fin2_drug_kernel(float* __restrict__ out,
                                 const float* __restrict__ deg,
                                 const float* __restrict__ b) {
    int i = blockIdx.x * blockDim.x + threadIdx.x;   // over ND*16 float4s
    if (i >= ND * 16) return;
    int row = i >> 4;
    int c4  = i & 15;
    float inv = 1.0f / fmaxf(deg[row], 1.0f);
    float4 v = ((float4*)out)[i];
    float4 bb = ((const float4*)b)[c4];
    v.x = v.x * inv + bb.x;
    v.y = v.y * inv + bb.y;
    v.z = v.z * inv + bb.z;
    v.w = v.w * inv + bb.w;
    ((float4*)out)[i] = v;
}

// o_p = out/deg_dpi + b_dpi + oagg_ppi/deg_ppi + b_ppi (in place on d_out+ND*64)
__global__ void fin2_prot_kernel(float* __restrict__ outp,
                                 const float* __restrict__ oagg,
                                 const float* __restrict__ deg1,
                                 const float* __restrict__ deg2,
                                 const float* __restrict__ b1,
                                 const float* __restrict__ b2) {
    int i = blockIdx.x * blockDim.x + threadIdx.x;   // over NP*16 float4s
    if (i >= NP * 16) return;
    int row = i >> 4;
    int c4  = i & 15;
    float inv1 = 1.0f / fmaxf(deg1[row], 1.0f);
    float inv2 = 1.0f / fmaxf(deg2[row], 1.0f);
    float4 v1 = ((float4*)outp)[i];
    float4 v2 = ((const float4*)oagg)[i];
    float4 bb1 = ((const float4*)b1)[c4];
    float4 bb2 = ((const float4*)b2)[c4];
    v1.x = v1.x * inv1 + bb1.x + v2.x * inv2 + bb2.x;
    v1.y = v1.y * inv1 + bb1.y + v2.y * inv2 + bb2.y;
    v1.z = v1.z * inv1 + bb1.z + v2.z * inv2 + bb2.z;
    v1.w = v1.w * inv1 + bb1.w + v2.w * inv2 + bb2.w;
    ((float4*)outp)[i] = v1;
}

// ---------------- launch ----------------

extern "C" void kernel_launch(void* const* d_in, const int* in_sizes, int n_in,
                              void* d_out, int out_size) {
    const float* x_drug = (const float*)d_in[0];
    const float* x_prot = (const float*)d_in[1];
    const int* src_ddi  = (const int*)d_in[2];
    const int* dst_ddi  = (const int*)d_in[3];
    const int* src_dpi  = (const int*)d_in[4];
    const int* dst_dpi  = (const int*)d_in[5];
    const int* src_ppi  = (const int*)d_in[6];
    const int* dst_ppi  = (const int*)d_in[7];
    const float* W1_ddi = (const float*)d_in[8];
    const float* b1_ddi = (const float*)d_in[9];
    const float* W1_dpi = (const float*)d_in[10];
    const float* b1_dpi = (const float*)d_in[11];
    const float* W1_ppi = (const float*)d_in[12];
    const float* b1_ppi = (const float*)d_in[13];
    const float* W2_ddi = (const float*)d_in[14];
    const float* b2_ddi = (const float*)d_in[15];
    const float* W2_dpi = (const float*)d_in[16];
    const float* b2_dpi = (const float*)d_in[17];
    const float* W2_ppi = (const float*)d_in[18];
    const float* b2_ppi = (const float*)d_in[19];
    float* out = (float*)d_out;

    float* B = nullptr;
    cudaGetSymbolAddress((void**)&B, g_buf);

    float* agg_d    = B + AGG_D;
    float* agg_p1   = B + AGG_P1;
    float* agg_p2   = B + AGG_P2;
    float* oagg_ppi = B + OAGG_PPI;
    float* deg_ddi  = B + DEG_DDI;
    float* deg_dpi  = B + DEG_DPI;
    float* deg_ppi  = B + DEG_PPI;
    float* t1_ddi   = B + T1_DDI;
    float* t1_dpi   = B + T1_DPI;
    float* t1_ppi   = B + T1_PPI;
    float* t2_ddi   = B + T2_DDI;
    float* t2_dpi   = B + T2_DPI;
    float* t2_ppi   = B + T2_PPI;

    // zero scratch (agg buffers + degrees) and output
    {
        int n4 = (int)(ZTOTAL / 4);
        zero_kernel<<<(n4 + 1023) / 1024, 1024>>>((float4*)B, n4);
        int o4 = (ND + NP) * DO / 4;
        zero_kernel<<<(o4 + 1023) / 1024, 1024>>>((float4*)out, o4);
    }

    // degrees (shared by both layers)
    degree_kernel<<<(EE + 255) / 256, 256>>>(dst_ddi, dst_dpi, dst_ppi,
                                             deg_ddi, deg_dpi, deg_ppi);

    // ---- layer 1 ----
    const int GB = (ND + 63) / 64;   // 782 (ND == NP)
    gemm_kernel<128><<<GB, 256>>>(x_drug, W1_ddi, t1_ddi, ND);
    gemm_kernel<128><<<GB, 256>>>(x_drug, W1_dpi, t1_dpi, ND);
    gemm_kernel<128><<<GB, 256>>>(x_prot, W1_ppi, t1_ppi, NP);

    const int SB = (EE * 32 + 255) / 256;  // one warp per edge
    scatter128_kernel<<<SB, 256>>>(t1_ddi, src_ddi, dst_ddi, agg_d);
    scatter128_kernel<<<SB, 256>>>(t1_dpi, src_dpi, dst_dpi, agg_p1);
    scatter128_kernel<<<SB, 256>>>(t1_ppi, src_ppi, dst_ppi, agg_p2);

    fin1_drug_kernel<<<(ND * 32 + 255) / 256, 256>>>(agg_d, deg_ddi, b1_ddi);
    fin1_prot_kernel<<<(NP * 32 + 255) / 256, 256>>>(agg_p1, agg_p2,
                                                     deg_dpi, deg_ppi,
                                                     b1_dpi, b1_ppi);

    // ---- layer 2 ----
    gemm_kernel<64><<<GB, 256>>>(agg_d,  W2_ddi, t2_ddi, ND);
    gemm_kernel<64><<<GB, 256>>>(agg_d,  W2_dpi, t2_dpi, ND);
    gemm_kernel<64><<<GB, 256>>>(agg_p1, W2_ppi, t2_ppi, NP);

    scatter64_kernel<<<SB, 256>>>(t2_ddi, src_ddi, dst_ddi, out);
    scatter64_kernel<<<SB, 256>>>(t2_dpi, src_dpi, dst_dpi, out + (size_t)ND * DO);
    scatter64_kernel<<<SB, 256>>>(t2_ppi, src_ppi, dst_ppi, oagg_ppi);

    fin2_drug_kernel<<<(ND * 16 + 255) / 256, 256>>>(out, deg_ddi, b2_ddi);
    fin2_prot_kernel<<<(NP * 16 + 255) / 256, 256>>>(out + (size_t)ND * DO, oagg_ppi,
                                                     deg_dpi, deg_ppi,
                                                     b2_dpi, b2_ppi);
}

// round 6
// speedup vs baseline: 2.1200x; 2.1200x over previous
#include <cuda_runtime.h>

#define ND 50000
#define NP 50000
#define NN 50000      // ND == NP
#define EE 600000
#define DIN 128
#define DH  128
#define DO  64

// ---------------- float scratch ----------------
constexpr size_t H_D    = 0;                                // [ND*DH] layer1 drug hidden
constexpr size_t H_P    = H_D    + (size_t)ND * DH;         // [NP*DH] layer1 prot hidden
constexpr size_t T1_DDI = H_P    + (size_t)NP * DH;         // [ND*DH]
constexpr size_t T1_DPI = T1_DDI + (size_t)ND * DH;
constexpr size_t T1_PPI = T1_DPI + (size_t)ND * DH;
constexpr size_t T2_DDI = T1_PPI + (size_t)NP * DH;         // [ND*DO]
constexpr size_t T2_DPI = T2_DDI + (size_t)ND * DO;
constexpr size_t T2_PPI = T2_DPI + (size_t)ND * DO;
constexpr size_t FTOTAL = T2_PPI + (size_t)NP * DO;

__device__ float g_buf[FTOTAL];

// ---------------- int scratch (CSR) ----------------
constexpr size_t DEG0 = 0;                  // [NN] each, x3 relations
constexpr size_t OFF0 = DEG0 + 3 * (size_t)NN;
constexpr size_t CUR0 = OFF0 + 3 * (size_t)NN;
constexpr size_t CSR0 = CUR0 + 3 * (size_t)NN;   // [EE] each
constexpr size_t ITOTAL = CSR0 + 3 * (size_t)EE;

__device__ int g_ibuf[ITOTAL];

// ---------------- CSR build ----------------

__global__ void zero_int_kernel(int* __restrict__ p, int n) {
    int i = blockIdx.x * blockDim.x + threadIdx.x;
    int stride = gridDim.x * blockDim.x;
    for (; i < n; i += stride) p[i] = 0;
}

__global__ void degree_kernel(const int* __restrict__ dst_ddi,
                              const int* __restrict__ dst_dpi,
                              const int* __restrict__ dst_ppi,
                              int* __restrict__ deg_ddi,
                              int* __restrict__ deg_dpi,
                              int* __restrict__ deg_ppi) {
    int i = blockIdx.x * blockDim.x + threadIdx.x;
    if (i < EE) {
        atomicAdd(&deg_ddi[dst_ddi[i]], 1);
        atomicAdd(&deg_dpi[dst_dpi[i]], 1);
        atomicAdd(&deg_ppi[dst_ppi[i]], 1);
    }
}

// one block per relation; exclusive scan of deg -> off, and cursor := off
__global__ void __launch_bounds__(1024) scan3_kernel(int* __restrict__ ibuf) {
    const int* deg = ibuf + DEG0 + (size_t)blockIdx.x * NN;
    int* off = ibuf + OFF0 + (size_t)blockIdx.x * NN;
    int* cur = ibuf + CUR0 + (size_t)blockIdx.x * NN;

    __shared__ int sh[1024];
    __shared__ int carry;
    int t = threadIdx.x;
    if (t == 0) carry = 0;
    __syncthreads();

    for (int base = 0; base < NN; base += 1024) {
        int x = (base + t < NN) ? deg[base + t] : 0;
        sh[t] = x;
        __syncthreads();
#pragma unroll
        for (int s = 1; s < 1024; s <<= 1) {
            int v = (t >= s) ? sh[t - s] : 0;
            __syncthreads();
            sh[t] += v;
            __syncthreads();
        }
        int excl = sh[t] - x;
        if (base + t < NN) {
            off[base + t] = carry + excl;
            cur[base + t] = carry + excl;
        }
        int tot = sh[1023];
        __syncthreads();
        if (t == 0) carry += tot;
        __syncthreads();
    }
}

__global__ void fill_csr_kernel(const int* __restrict__ src,
                                const int* __restrict__ dst,
                                int* __restrict__ cursor,
                                int* __restrict__ csr) {
    int i = blockIdx.x * blockDim.x + threadIdx.x;
    if (i < EE) {
        int p = atomicAdd(&cursor[dst[i]], 1);
        csr[p] = src[i];
    }
}

// ---------------- GEMMs ----------------

// single-output: C[M x N] = A[M x 128] @ W[128 x N]
template <int N>
__global__ void __launch_bounds__(256) gemm_kernel(const float* __restrict__ A,
                                                   const float* __restrict__ W,
                                                   float* __restrict__ C, int M) {
    constexpr int BM = 64;
    constexpr int K  = 128;
    constexpr int BK = 32;
    constexpr int NTX = N / 4;
    constexpr int NTY = 256 / NTX;
    constexpr int TM  = BM / NTY;

    __shared__ float As[BM * K];
    __shared__ float Ws[BK * N];

    int tid = threadIdx.x;
    int m0  = blockIdx.x * BM;
    int rows = M - m0; if (rows > BM) rows = BM;

    const float4* A4 = (const float4*)(A + (size_t)m0 * K);
    for (int i = tid; i < rows * (K / 4); i += 256)
        ((float4*)As)[i] = A4[i];

    int tx = tid % NTX;
    int ty = tid / NTX;
    float acc[TM][4];
#pragma unroll
    for (int r = 0; r < TM; r++) { acc[r][0]=0.f; acc[r][1]=0.f; acc[r][2]=0.f; acc[r][3]=0.f; }

    for (int kk = 0; kk < K; kk += BK) {
        __syncthreads();
        const float4* W4 = (const float4*)(W + (size_t)kk * N);
        for (int i = tid; i < BK * N / 4; i += 256)
            ((float4*)Ws)[i] = W4[i];
        __syncthreads();
#pragma unroll
        for (int k = 0; k < BK; k++) {
            float4 w = ((const float4*)Ws)[k * (N / 4) + tx];
#pragma unroll
            for (int r = 0; r < TM; r++) {
                float a = As[(ty * TM + r) * K + kk + k];
                acc[r][0] += a * w.x;
                acc[r][1] += a * w.y;
                acc[r][2] += a * w.z;
                acc[r][3] += a * w.w;
            }
        }
    }

#pragma unroll
    for (int r = 0; r < TM; r++) {
        int m = m0 + ty * TM + r;
        if (m < M) {
            float4 o = make_float4(acc[r][0], acc[r][1], acc[r][2], acc[r][3]);
            ((float4*)(C + (size_t)m * N))[tx] = o;
        }
    }
}

// dual-output: Ca = A@Wa, Cb = A@Wb (A tile loaded once; 2x arithmetic intensity)
template <int N, int BK>
__global__ void __launch_bounds__(256) gemm_dual_kernel(const float* __restrict__ A,
                                                        const float* __restrict__ Wa,
                                                        const float* __restrict__ Wb,
                                                        float* __restrict__ Ca,
                                                        float* __restrict__ Cb, int M) {
    constexpr int BM = 64;
    constexpr int K  = 128;
    constexpr int NTX = N / 4;
    constexpr int NTY = 256 / NTX;
    constexpr int TM  = BM / NTY;

    __shared__ float As[BM * K];        // 32 KB
    __shared__ float Wsa[BK * N];       // 8 KB each (N=128,BK=16 or N=64,BK=32)
    __shared__ float Wsb[BK * N];

    int tid = threadIdx.x;
    int m0  = blockIdx.x * BM;
    int rows = M - m0; if (rows > BM) rows = BM;

    const float4* A4 = (const float4*)(A + (size_t)m0 * K);
    for (int i = tid; i < rows * (K / 4); i += 256)
        ((float4*)As)[i] = A4[i];

    int tx = tid % NTX;
    int ty = tid / NTX;
    float accA[TM][4], accB[TM][4];
#pragma unroll
    for (int r = 0; r < TM; r++) {
        accA[r][0]=0.f; accA[r][1]=0.f; accA[r][2]=0.f; accA[r][3]=0.f;
        accB[r][0]=0.f; accB[r][1]=0.f; accB[r][2]=0.f; accB[r][3]=0.f;
    }

    for (int kk = 0; kk < K; kk += BK) {
        __syncthreads();
        const float4* Wa4 = (const float4*)(Wa + (size_t)kk * N);
        const float4* Wb4 = (const float4*)(Wb + (size_t)kk * N);
        for (int i = tid; i < BK * N / 4; i += 256) {
            ((float4*)Wsa)[i] = Wa4[i];
            ((float4*)Wsb)[i] = Wb4[i];
        }
        __syncthreads();
#pragma unroll
        for (int k = 0; k < BK; k++) {
            float4 wa = ((const float4*)Wsa)[k * (N / 4) + tx];
            float4 wb = ((const float4*)Wsb)[k * (N / 4) + tx];
#pragma unroll
            for (int r = 0; r < TM; r++) {
                float a = As[(ty * TM + r) * K + kk + k];
                accA[r][0] += a * wa.x; accA[r][1] += a * wa.y;
                accA[r][2] += a * wa.z; accA[r][3] += a * wa.w;
                accB[r][0] += a * wb.x; accB[r][1] += a * wb.y;
                accB[r][2] += a * wb.z; accB[r][3] += a * wb.w;
            }
        }
    }

#pragma unroll
    for (int r = 0; r < TM; r++) {
        int m = m0 + ty * TM + r;
        if (m < M) {
            ((float4*)(Ca + (size_t)m * N))[tx] =
                make_float4(accA[r][0], accA[r][1], accA[r][2], accA[r][3]);
            ((float4*)(Cb + (size_t)m * N))[tx] =
                make_float4(accB[r][0], accB[r][1], accB[r][2], accB[r][3]);
        }
    }
}

// ---- gather aggregation: one warp per dst node ----

__global__ void __launch_bounds__(256) agg128_kernel(const float* __restrict__ t,
                                                     const int* __restrict__ csr,
                                                     const int* __restrict__ off,
                                                     const int* __restrict__ deg,
                                                     const float* __restrict__ b,
                                                     float* __restrict__ out, int n) {
    int gw   = (blockIdx.x * blockDim.x + threadIdx.x) >> 5;
    int lane = threadIdx.x & 31;
    if (gw >= n) return;
    int o  = __ldg(&off[gw]);
    int dg = __ldg(&deg[gw]);
    int e  = o + dg;
    float4 acc = make_float4(0.f, 0.f, 0.f, 0.f);
    int i = o;
    for (; i + 1 < e; i += 2) {
        int s0 = __ldg(&csr[i]);
        int s1 = __ldg(&csr[i + 1]);
        float4 v0 = __ldg((const float4*)(t + (size_t)s0 * 128) + lane);
        float4 v1 = __ldg((const float4*)(t + (size_t)s1 * 128) + lane);
        acc.x += v0.x + v1.x; acc.y += v0.y + v1.y;
        acc.z += v0.z + v1.z; acc.w += v0.w + v1.w;
    }
    if (i < e) {
        int s = __ldg(&csr[i]);
        float4 v = __ldg((const float4*)(t + (size_t)s * 128) + lane);
        acc.x += v.x; acc.y += v.y; acc.z += v.z; acc.w += v.w;
    }
    float inv = 1.0f / fmaxf((float)dg, 1.0f);
    float4 bb = __ldg((const float4*)b + lane);
    float4 r = make_float4(acc.x * inv + bb.x, acc.y * inv + bb.y,
                           acc.z * inv + bb.z, acc.w * inv + bb.w);
    ((float4*)(out + (size_t)gw * 128))[lane] = r;
}

__global__ void __launch_bounds__(256) agg128_dual_kernel(
        const float* __restrict__ tA, const int* __restrict__ csrA,
        const int* __restrict__ offA, const int* __restrict__ degA,
        const float* __restrict__ bA,
        const float* __restrict__ tB, const int* __restrict__ csrB,
        const int* __restrict__ offB, const int* __restrict__ degB,
        const float* __restrict__ bB,
        float* __restrict__ out, int n) {
    int gw   = (blockIdx.x * blockDim.x + threadIdx.x) >> 5;
    int lane = threadIdx.x & 31;
    if (gw >= n) return;

    float4 accA = make_float4(0.f, 0.f, 0.f, 0.f);
    {
        int o = __ldg(&offA[gw]); int dg = __ldg(&degA[gw]); int e = o + dg;
        int i = o;
        for (; i + 1 < e; i += 2) {
            int s0 = __ldg(&csrA[i]);
            int s1 = __ldg(&csrA[i + 1]);
            float4 v0 = __ldg((const float4*)(tA + (size_t)s0 * 128) + lane);
            float4 v1 = __ldg((const float4*)(tA + (size_t)s1 * 128) + lane);
            accA.x += v0.x + v1.x; accA.y += v0.y + v1.y;
            accA.z += v0.z + v1.z; accA.w += v0.w + v1.w;
        }
        if (i < e) {
            int s = __ldg(&csrA[i]);
            float4 v = __ldg((const float4*)(tA + (size_t)s * 128) + lane);
            accA.x += v.x; accA.y += v.y; accA.z += v.z; accA.w += v.w;
        }
    }
    float4 accB = make_float4(0.f, 0.f, 0.f, 0.f);
    {
        int o = __ldg(&offB[gw]); int dg = __ldg(&degB[gw]); int e = o + dg;
        int i = o;
        for (; i + 1 < e; i += 2) {
            int s0 = __ldg(&csrB[i]);
            int s1 = __ldg(&csrB[i + 1]);
            float4 v0 = __ldg((const float4*)(tB + (size_t)s0 * 128) + lane);
            float4 v1 = __ldg((const float4*)(tB + (size_t)s1 * 128) + lane);
            accB.x += v0.x + v1.x; accB.y += v0.y + v1.y;
            accB.z += v0.z + v1.z; accB.w += v0.w + v1.w;
        }
        if (i < e) {
            int s = __ldg(&csrB[i]);
            float4 v = __ldg((const float4*)(tB + (size_t)s * 128) + lane);
            accB.x += v.x; accB.y += v.y; accB.z += v.z; accB.w += v.w;
        }
    }
    float invA = 1.0f / fmaxf((float)__ldg(&degA[gw]), 1.0f);
    float invB = 1.0f / fmaxf((float)__ldg(&degB[gw]), 1.0f);
    float4 bbA = __ldg((const float4*)bA + lane);
    float4 bbB = __ldg((const float4*)bB + lane);
    float4 r = make_float4(accA.x * invA + bbA.x + accB.x * invB + bbB.x,
                           accA.y * invA + bbA.y + accB.y * invB + bbB.y,
                           accA.z * invA + bbA.z + accB.z * invB + bbB.z,
                           accA.w * invA + bbA.w + accB.w * invB + bbB.w);
    ((float4*)(out + (size_t)gw * 128))[lane] = r;
}

__global__ void __launch_bounds__(256) agg64_kernel(const float* __restrict__ t,
                                                    const int* __restrict__ csr,
                                                    const int* __restrict__ off,
                                                    const int* __restrict__ deg,
                                                    const float* __restrict__ b,
                                                    float* __restrict__ out, int n) {
    int gw   = (blockIdx.x * blockDim.x + threadIdx.x) >> 5;
    int lane = threadIdx.x & 31;
    if (gw >= n) return;
    int o  = __ldg(&off[gw]);
    int dg = __ldg(&deg[gw]);
    int e  = o + dg;
    float2 acc = make_float2(0.f, 0.f);
    int i = o;
    for (; i + 1 < e; i += 2) {
        int s0 = __ldg(&csr[i]);
        int s1 = __ldg(&csr[i + 1]);
        float2 v0 = __ldg((const float2*)(t + (size_t)s0 * 64) + lane);
        float2 v1 = __ldg((const float2*)(t + (size_t)s1 * 64) + lane);
        acc.x += v0.x + v1.x; acc.y += v0.y + v1.y;
    }
    if (i < e) {
        int s = __ldg(&csr[i]);
        float2 v = __ldg((const float2*)(t + (size_t)s * 64) + lane);
        acc.x += v.x; acc.y += v.y;
    }
    float inv = 1.0f / fmaxf((float)dg, 1.0f);
    float2 bb = __ldg((const float2*)b + lane);
    ((float2*)(out + (size_t)gw * 64))[lane] =
        make_float2(acc.x * inv + bb.x, acc.y * inv + bb.y);
}

__global__ void __launch_bounds__(256) agg64_dual_kernel(
        const float* __restrict__ tA, const int* __restrict__ csrA,
        const int* __restrict__ offA, const int* __restrict__ degA,
        const float* __restrict__ bA,
        const float* __restrict__ tB, const int* __restrict__ csrB,
        const int* __restrict__ offB, const int* __restrict__ degB,
        const float* __restrict__ bB,
        float* __restrict__ out, int n) {
    int gw   = (blockIdx.x * blockDim.x + threadIdx.x) >> 5;
    int lane = threadIdx.x & 31;
    if (gw >= n) return;

    float2 accA = make_float2(0.f, 0.f);
    {
        int o = __ldg(&offA[gw]); int dg = __ldg(&degA[gw]); int e = o + dg;
        int i = o;
        for (; i + 1 < e; i += 2) {
            int s0 = __ldg(&csrA[i]);
            int s1 = __ldg(&csrA[i + 1]);
            float2 v0 = __ldg((const float2*)(tA + (size_t)s0 * 64) + lane);
            float2 v1 = __ldg((const float2*)(tA + (size_t)s1 * 64) + lane);
            accA.x += v0.x + v1.x; accA.y += v0.y + v1.y;
        }
        if (i < e) {
            int s = __ldg(&csrA[i]);
            float2 v = __ldg((const float2*)(tA + (size_t)s * 64) + lane);
            accA.x += v.x; accA.y += v.y;
        }
    }
    float2 accB = make_float2(0.f, 0.f);
    {
        int o = __ldg(&offB[gw]); int dg = __ldg(&degB[gw]); int e = o + dg;
        int i = o;
        for (; i + 1 < e; i += 2) {
            int s0 = __ldg(&csrB[i]);
            int s1 = __ldg(&csrB[i + 1]);
            float2 v0 = __ldg((const float2*)(tB + (size_t)s0 * 64) + lane);
            float2 v1 = __ldg((const float2*)(tB + (size_t)s1 * 64) + lane);
            accB.x += v0.x + v1.x; accB.y += v0.y + v1.y;
        }
        if (i < e) {
            int s = __ldg(&csrB[i]);
            float2 v = __ldg((const float2*)(tB + (size_t)s * 64) + lane);
            accB.x += v.x; accB.y += v.y;
        }
    }
    float invA = 1.0f / fmaxf((float)__ldg(&degA[gw]), 1.0f);
    float invB = 1.0f / fmaxf((float)__ldg(&degB[gw]), 1.0f);
    float2 bbA = __ldg((const float2*)bA + lane);
    float2 bbB = __ldg((const float2*)bB + lane);
    ((float2*)(out + (size_t)gw * 64))[lane] =
        make_float2(accA.x * invA + bbA.x + accB.x * invB + bbB.x,
                    accA.y * invA + bbA.y + accB.y * invB + bbB.y);
}

// ---------------- launch ----------------

extern "C" void kernel_launch(void* const* d_in, const int* in_sizes, int n_in,
                              void* d_out, int out_size) {
    const float* x_drug = (const float*)d_in[0];
    const float* x_prot = (const float*)d_in[1];
    const int* src_ddi  = (const int*)d_in[2];
    const int* dst_ddi  = (const int*)d_in[3];
    const int* src_dpi  = (const int*)d_in[4];
    const int* dst_dpi  = (const int*)d_in[5];
    const int* src_ppi  = (const int*)d_in[6];
    const int* dst_ppi  = (const int*)d_in[7];
    const float* W1_ddi = (const float*)d_in[8];
    const float* b1_ddi = (const float*)d_in[9];
    const float* W1_dpi = (const float*)d_in[10];
    const float* b1_dpi = (const float*)d_in[11];
    const float* W1_ppi = (const float*)d_in[12];
    const float* b1_ppi = (const float*)d_in[13];
    const float* W2_ddi = (const float*)d_in[14];
    const float* b2_ddi = (const float*)d_in[15];
    const float* W2_dpi = (const float*)d_in[16];
    const float* b2_dpi = (const float*)d_in[17];
    const float* W2_ppi = (const float*)d_in[18];
    const float* b2_ppi = (const float*)d_in[19];
    float* out = (float*)d_out;

    float* B = nullptr;
    cudaGetSymbolAddress((void**)&B, g_buf);
    int* IB = nullptr;
    cudaGetSymbolAddress((void**)&IB, g_ibuf);

    float* h_d    = B + H_D;
    float* h_p    = B + H_P;
    float* t1_ddi = B + T1_DDI;
    float* t1_dpi = B + T1_DPI;
    float* t1_ppi = B + T1_PPI;
    float* t2_ddi = B + T2_DDI;
    float* t2_dpi = B + T2_DPI;
    float* t2_ppi = B + T2_PPI;

    int* deg_ddi = IB + DEG0;
    int* deg_dpi = IB + DEG0 + NN;
    int* deg_ppi = IB + DEG0 + 2 * NN;
    int* off_ddi = IB + OFF0;
    int* off_dpi = IB + OFF0 + NN;
    int* off_ppi = IB + OFF0 + 2 * NN;
    int* cur_ddi = IB + CUR0;
    int* cur_dpi = IB + CUR0 + NN;
    int* cur_ppi = IB + CUR0 + 2 * NN;
    int* csr_ddi = IB + CSR0;
    int* csr_dpi = IB + CSR0 + EE;
    int* csr_ppi = IB + CSR0 + 2 * EE;

    // ---- build CSR (3 relations) ----
    zero_int_kernel<<<64, 1024>>>(IB + DEG0, 3 * NN);
    degree_kernel<<<(EE + 255) / 256, 256>>>(dst_ddi, dst_dpi, dst_ppi,
                                             deg_ddi, deg_dpi, deg_ppi);
    scan3_kernel<<<3, 1024>>>(IB);
    fill_csr_kernel<<<(EE + 255) / 256, 256>>>(src_ddi, dst_ddi, cur_ddi, csr_ddi);
    fill_csr_kernel<<<(EE + 255) / 256, 256>>>(src_dpi, dst_dpi, cur_dpi, csr_dpi);
    fill_csr_kernel<<<(EE + 255) / 256, 256>>>(src_ppi, dst_ppi, cur_ppi, csr_ppi);

    // ---- layer 1 ----
    const int GB = (NN + 63) / 64;
    gemm_dual_kernel<128, 16><<<GB, 256>>>(x_drug, W1_ddi, W1_dpi, t1_ddi, t1_dpi, ND);
    gemm_kernel<128><<<GB, 256>>>(x_prot, W1_ppi, t1_ppi, NP);

    const int AB = (NN * 32 + 255) / 256;
    agg128_kernel<<<AB, 256>>>(t1_ddi, csr_ddi, off_ddi, deg_ddi, b1_ddi, h_d, ND);
    agg128_dual_kernel<<<AB, 256>>>(t1_dpi, csr_dpi, off_dpi, deg_dpi, b1_dpi,
                                    t1_ppi, csr_ppi, off_ppi, deg_ppi, b1_ppi,
                                    h_p, NP);

    // ---- layer 2 ----
    gemm_dual_kernel<64, 32><<<GB, 256>>>(h_d, W2_ddi, W2_dpi, t2_ddi, t2_dpi, ND);
    gemm_kernel<64><<<GB, 256>>>(h_p, W2_ppi, t2_ppi, NP);

    agg64_kernel<<<AB, 256>>>(t2_ddi, csr_ddi, off_ddi, deg_ddi, b2_ddi, out, ND);
    agg64_dual_kernel<<<AB, 256>>>(t2_dpi, csr_dpi, off_dpi, deg_dpi, b2_dpi,
                                   t2_ppi, csr_ppi, off_ppi, deg_ppi, b2_ppi,
                                   out + (size_t)ND * DO, NP);
}

// round 7
// speedup vs baseline: 2.3634x; 1.1148x over previous
#include <cuda_runtime.h>

#define ND 50000
#define NP 50000
#define NN 50000      // ND == NP
#define EE 600000
#define DIN 128
#define DH  128
#define DO  64

// ---------------- float scratch ----------------
constexpr size_t H_D    = 0;                                // [ND*DH] layer1 drug hidden
constexpr size_t H_P    = H_D    + (size_t)ND * DH;         // [NP*DH] layer1 prot hidden
constexpr size_t T1_DDI = H_P    + (size_t)NP * DH;         // [ND*DH]
constexpr size_t T1_DPI = T1_DDI + (size_t)ND * DH;
constexpr size_t T1_PPI = T1_DPI + (size_t)ND * DH;
constexpr size_t T2_DDI = T1_PPI + (size_t)NP * DH;         // [ND*DO]
constexpr size_t T2_DPI = T2_DDI + (size_t)ND * DO;
constexpr size_t T2_PPI = T2_DPI + (size_t)ND * DO;
constexpr size_t FTOTAL = T2_PPI + (size_t)NP * DO;

__device__ float g_buf[FTOTAL];

// ---------------- int scratch (CSR) ----------------
constexpr size_t DEG0 = 0;                  // [NN] each, x3 relations
constexpr size_t OFF0 = DEG0 + 3 * (size_t)NN;
constexpr size_t CUR0 = OFF0 + 3 * (size_t)NN;
constexpr size_t CSR0 = CUR0 + 3 * (size_t)NN;   // [EE] each
constexpr size_t ITOTAL = CSR0 + 3 * (size_t)EE;

__device__ int g_ibuf[ITOTAL];

// ---------------- CSR build ----------------

__global__ void zero_int_kernel(int* __restrict__ p, int n) {
    int i = blockIdx.x * blockDim.x + threadIdx.x;
    int stride = gridDim.x * blockDim.x;
    for (; i < n; i += stride) p[i] = 0;
}

__global__ void degree_kernel(const int* __restrict__ dst_ddi,
                              const int* __restrict__ dst_dpi,
                              const int* __restrict__ dst_ppi,
                              int* __restrict__ deg_ddi,
                              int* __restrict__ deg_dpi,
                              int* __restrict__ deg_ppi) {
    int i = blockIdx.x * blockDim.x + threadIdx.x;
    if (i < EE) {
        atomicAdd(&deg_ddi[dst_ddi[i]], 1);
        atomicAdd(&deg_dpi[dst_dpi[i]], 1);
        atomicAdd(&deg_ppi[dst_ppi[i]], 1);
    }
}

// one block per relation; warp-shuffle exclusive scan of deg -> off, cursor := off
__global__ void __launch_bounds__(1024) scan3_kernel(int* __restrict__ ibuf) {
    const int* deg = ibuf + DEG0 + (size_t)blockIdx.x * NN;
    int* off = ibuf + OFF0 + (size_t)blockIdx.x * NN;
    int* cur = ibuf + CUR0 + (size_t)blockIdx.x * NN;

    __shared__ int warp_tot[32];
    __shared__ int carry_sh;
    int t = threadIdx.x;
    int lane = t & 31;
    int wid  = t >> 5;
    if (t == 0) carry_sh = 0;
    __syncthreads();

    for (int base = 0; base < NN; base += 1024) {
        int x = (base + t < NN) ? deg[base + t] : 0;
        // warp inclusive scan
        int v = x;
#pragma unroll
        for (int s = 1; s < 32; s <<= 1) {
            int y = __shfl_up_sync(0xffffffffu, v, s);
            if (lane >= s) v += y;
        }
        if (lane == 31) warp_tot[wid] = v;
        __syncthreads();
        if (wid == 0) {
            int w = warp_tot[lane];
#pragma unroll
            for (int s = 1; s < 32; s <<= 1) {
                int y = __shfl_up_sync(0xffffffffu, w, s);
                if (lane >= s) w += y;
            }
            warp_tot[lane] = w;    // inclusive scan of warp totals
        }
        __syncthreads();
        int warp_off = (wid == 0) ? 0 : warp_tot[wid - 1];
        int excl = v - x + warp_off;
        int c = carry_sh;
        if (base + t < NN) {
            off[base + t] = c + excl;
            cur[base + t] = c + excl;
        }
        int tile_tot = warp_tot[31];
        __syncthreads();
        if (t == 0) carry_sh = c + tile_tot;
        __syncthreads();
    }
}

// all 3 relations in one launch: overlap the ATOMG latencies
__global__ void fill_csr3_kernel(const int* __restrict__ s0, const int* __restrict__ d0,
                                 int* __restrict__ c0, int* __restrict__ r0,
                                 const int* __restrict__ s1, const int* __restrict__ d1,
                                 int* __restrict__ c1, int* __restrict__ r1,
                                 const int* __restrict__ s2, const int* __restrict__ d2,
                                 int* __restrict__ c2, int* __restrict__ r2) {
    int i = blockIdx.x * blockDim.x + threadIdx.x;
    if (i < EE) {
        int p = atomicAdd(&c0[d0[i]], 1);
        r0[p] = s0[i];
    } else if (i < 2 * EE) {
        int j = i - EE;
        int p = atomicAdd(&c1[d1[j]], 1);
        r1[p] = s1[j];
    } else if (i < 3 * EE) {
        int j = i - 2 * EE;
        int p = atomicAdd(&c2[d2[j]], 1);
        r2[p] = s2[j];
    }
}

// ---------------- GEMMs ----------------

// single-output: C[M x N] = A[M x 128] @ W[128 x N]
template <int N>
__global__ void __launch_bounds__(256) gemm_kernel(const float* __restrict__ A,
                                                   const float* __restrict__ W,
                                                   float* __restrict__ C, int M) {
    constexpr int BM = 64;
    constexpr int K  = 128;
    constexpr int BK = 32;
    constexpr int NTX = N / 4;
    constexpr int NTY = 256 / NTX;
    constexpr int TM  = BM / NTY;

    __shared__ float As[BM * K];
    __shared__ float Ws[BK * N];

    int tid = threadIdx.x;
    int m0  = blockIdx.x * BM;
    int rows = M - m0; if (rows > BM) rows = BM;

    const float4* A4 = (const float4*)(A + (size_t)m0 * K);
    for (int i = tid; i < rows * (K / 4); i += 256)
        ((float4*)As)[i] = A4[i];

    int tx = tid % NTX;
    int ty = tid / NTX;
    float acc[TM][4];
#pragma unroll
    for (int r = 0; r < TM; r++) { acc[r][0]=0.f; acc[r][1]=0.f; acc[r][2]=0.f; acc[r][3]=0.f; }

    for (int kk = 0; kk < K; kk += BK) {
        __syncthreads();
        const float4* W4 = (const float4*)(W + (size_t)kk * N);
        for (int i = tid; i < BK * N / 4; i += 256)
            ((float4*)Ws)[i] = W4[i];
        __syncthreads();
#pragma unroll
        for (int k = 0; k < BK; k++) {
            float4 w = ((const float4*)Ws)[k * (N / 4) + tx];
#pragma unroll
            for (int r = 0; r < TM; r++) {
                float a = As[(ty * TM + r) * K + kk + k];
                acc[r][0] += a * w.x;
                acc[r][1] += a * w.y;
                acc[r][2] += a * w.z;
                acc[r][3] += a * w.w;
            }
        }
    }

#pragma unroll
    for (int r = 0; r < TM; r++) {
        int m = m0 + ty * TM + r;
        if (m < M) {
            float4 o = make_float4(acc[r][0], acc[r][1], acc[r][2], acc[r][3]);
            ((float4*)(C + (size_t)m * N))[tx] = o;
        }
    }
}

// dual-output: Ca = A@Wa, Cb = A@Wb (A tile loaded once)
template <int N, int BK>
__global__ void __launch_bounds__(256) gemm_dual_kernel(const float* __restrict__ A,
                                                        const float* __restrict__ Wa,
                                                        const float* __restrict__ Wb,
                                                        float* __restrict__ Ca,
                                                        float* __restrict__ Cb, int M) {
    constexpr int BM = 64;
    constexpr int K  = 128;
    constexpr int NTX = N / 4;
    constexpr int NTY = 256 / NTX;
    constexpr int TM  = BM / NTY;

    __shared__ float As[BM * K];
    __shared__ float Wsa[BK * N];
    __shared__ float Wsb[BK * N];

    int tid = threadIdx.x;
    int m0  = blockIdx.x * BM;
    int rows = M - m0; if (rows > BM) rows = BM;

    const float4* A4 = (const float4*)(A + (size_t)m0 * K);
    for (int i = tid; i < rows * (K / 4); i += 256)
        ((float4*)As)[i] = A4[i];

    int tx = tid % NTX;
    int ty = tid / NTX;
    float accA[TM][4], accB[TM][4];
#pragma unroll
    for (int r = 0; r < TM; r++) {
        accA[r][0]=0.f; accA[r][1]=0.f; accA[r][2]=0.f; accA[r][3]=0.f;
        accB[r][0]=0.f; accB[r][1]=0.f; accB[r][2]=0.f; accB[r][3]=0.f;
    }

    for (int kk = 0; kk < K; kk += BK) {
        __syncthreads();
        const float4* Wa4 = (const float4*)(Wa + (size_t)kk * N);
        const float4* Wb4 = (const float4*)(Wb + (size_t)kk * N);
        for (int i = tid; i < BK * N / 4; i += 256) {
            ((float4*)Wsa)[i] = Wa4[i];
            ((float4*)Wsb)[i] = Wb4[i];
        }
        __syncthreads();
#pragma unroll
        for (int k = 0; k < BK; k++) {
            float4 wa = ((const float4*)Wsa)[k * (N / 4) + tx];
            float4 wb = ((const float4*)Wsb)[k * (N / 4) + tx];
#pragma unroll
            for (int r = 0; r < TM; r++) {
                float a = As[(ty * TM + r) * K + kk + k];
                accA[r][0] += a * wa.x; accA[r][1] += a * wa.y;
                accA[r][2] += a * wa.z; accA[r][3] += a * wa.w;
                accB[r][0] += a * wb.x; accB[r][1] += a * wb.y;
                accB[r][2] += a * wb.z; accB[r][3] += a * wb.w;
            }
        }
    }

#pragma unroll
    for (int r = 0; r < TM; r++) {
        int m = m0 + ty * TM + r;
        if (m < M) {
            ((float4*)(Ca + (size_t)m * N))[tx] =
                make_float4(accA[r][0], accA[r][1], accA[r][2], accA[r][3]);
            ((float4*)(Cb + (size_t)m * N))[tx] =
                make_float4(accB[r][0], accB[r][1], accB[r][2], accB[r][3]);
        }
    }
}

// ---- gather aggregation ----

// 128-dim: one warp per dst node, float4 per lane, 4-deep unroll for MLP
__global__ void __launch_bounds__(256) agg128_kernel(const float* __restrict__ t,
                                                     const int* __restrict__ csr,
                                                     const int* __restrict__ off,
                                                     const int* __restrict__ deg,
                                                     const float* __restrict__ b,
                                                     float* __restrict__ out, int n) {
    int gw   = (blockIdx.x * blockDim.x + threadIdx.x) >> 5;
    int lane = threadIdx.x & 31;
    if (gw >= n) return;
    int o  = __ldg(&off[gw]);
    int dg = __ldg(&deg[gw]);
    int e  = o + dg;
    float4 acc = make_float4(0.f, 0.f, 0.f, 0.f);
    int i = o;
    for (; i + 3 < e; i += 4) {
        int s0 = __ldg(&csr[i]);
        int s1 = __ldg(&csr[i + 1]);
        int s2 = __ldg(&csr[i + 2]);
        int s3 = __ldg(&csr[i + 3]);
        float4 v0 = __ldg((const float4*)(t + (size_t)s0 * 128) + lane);
        float4 v1 = __ldg((const float4*)(t + (size_t)s1 * 128) + lane);
        float4 v2 = __ldg((const float4*)(t + (size_t)s2 * 128) + lane);
        float4 v3 = __ldg((const float4*)(t + (size_t)s3 * 128) + lane);
        acc.x += (v0.x + v1.x) + (v2.x + v3.x);
        acc.y += (v0.y + v1.y) + (v2.y + v3.y);
        acc.z += (v0.z + v1.z) + (v2.z + v3.z);
        acc.w += (v0.w + v1.w) + (v2.w + v3.w);
    }
    for (; i < e; i++) {
        int s = __ldg(&csr[i]);
        float4 v = __ldg((const float4*)(t + (size_t)s * 128) + lane);
        acc.x += v.x; acc.y += v.y; acc.z += v.z; acc.w += v.w;
    }
    float inv = 1.0f / fmaxf((float)dg, 1.0f);
    float4 bb = __ldg((const float4*)b + lane);
    ((float4*)(out + (size_t)gw * 128))[lane] =
        make_float4(acc.x * inv + bb.x, acc.y * inv + bb.y,
                    acc.z * inv + bb.z, acc.w * inv + bb.w);
}

__global__ void __launch_bounds__(256) agg128_dual_kernel(
        const float* __restrict__ tA, const int* __restrict__ csrA,
        const int* __restrict__ offA, const int* __restrict__ degA,
        const float* __restrict__ bA,
        const float* __restrict__ tB, const int* __restrict__ csrB,
        const int* __restrict__ offB, const int* __restrict__ degB,
        const float* __restrict__ bB,
        float* __restrict__ out, int n) {
    int gw   = (blockIdx.x * blockDim.x + threadIdx.x) >> 5;
    int lane = threadIdx.x & 31;
    if (gw >= n) return;

    int dgA = __ldg(&degA[gw]);
    int dgB = __ldg(&degB[gw]);

    float4 accA = make_float4(0.f, 0.f, 0.f, 0.f);
    {
        int o = __ldg(&offA[gw]); int e = o + dgA;
        int i = o;
        for (; i + 3 < e; i += 4) {
            int s0 = __ldg(&csrA[i]);
            int s1 = __ldg(&csrA[i + 1]);
            int s2 = __ldg(&csrA[i + 2]);
            int s3 = __ldg(&csrA[i + 3]);
            float4 v0 = __ldg((const float4*)(tA + (size_t)s0 * 128) + lane);
            float4 v1 = __ldg((const float4*)(tA + (size_t)s1 * 128) + lane);
            float4 v2 = __ldg((const float4*)(tA + (size_t)s2 * 128) + lane);
            float4 v3 = __ldg((const float4*)(tA + (size_t)s3 * 128) + lane);
            accA.x += (v0.x + v1.x) + (v2.x + v3.x);
            accA.y += (v0.y + v1.y) + (v2.y + v3.y);
            accA.z += (v0.z + v1.z) + (v2.z + v3.z);
            accA.w += (v0.w + v1.w) + (v2.w + v3.w);
        }
        for (; i < e; i++) {
            int s = __ldg(&csrA[i]);
            float4 v = __ldg((const float4*)(tA + (size_t)s * 128) + lane);
            accA.x += v.x; accA.y += v.y; accA.z += v.z; accA.w += v.w;
        }
    }
    float4 accB = make_float4(0.f, 0.f, 0.f, 0.f);
    {
        int o = __ldg(&offB[gw]); int e = o + dgB;
        int i = o;
        for (; i + 3 < e; i += 4) {
            int s0 = __ldg(&csrB[i]);
            int s1 = __ldg(&csrB[i + 1]);
            int s2 = __ldg(&csrB[i + 2]);
            int s3 = __ldg(&csrB[i + 3]);
            float4 v0 = __ldg((const float4*)(tB + (size_t)s0 * 128) + lane);
            float4 v1 = __ldg((const float4*)(tB + (size_t)s1 * 128) + lane);
            float4 v2 = __ldg((const float4*)(tB + (size_t)s2 * 128) + lane);
            float4 v3 = __ldg((const float4*)(tB + (size_t)s3 * 128) + lane);
            accB.x += (v0.x + v1.x) + (v2.x + v3.x);
            accB.y += (v0.y + v1.y) + (v2.y + v3.y);
            accB.z += (v0.z + v1.z) + (v2.z + v3.z);
            accB.w += (v0.w + v1.w) + (v2.w + v3.w);
        }
        for (; i < e; i++) {
            int s = __ldg(&csrB[i]);
            float4 v = __ldg((const float4*)(tB + (size_t)s * 128) + lane);
            accB.x += v.x; accB.y += v.y; accB.z += v.z; accB.w += v.w;
        }
    }
    float invA = 1.0f / fmaxf((float)dgA, 1.0f);
    float invB = 1.0f / fmaxf((float)dgB, 1.0f);
    float4 bbA = __ldg((const float4*)bA + lane);
    float4 bbB = __ldg((const float4*)bB + lane);
    ((float4*)(out + (size_t)gw * 128))[lane] =
        make_float4(accA.x * invA + bbA.x + accB.x * invB + bbB.x,
                    accA.y * invA + bbA.y + accB.y * invB + bbB.y,
                    accA.z * invA + bbA.z + accB.z * invB + bbB.z,
                    accA.w * invA + bbA.w + accB.w * invB + bbB.w);
}

// 64-dim: one warp per node, 16 lanes per edge (float4), 2 edge slots per warp.
// half = lane>>4 selects edge slot; final shfl_xor(16) combines the two slots.
__global__ void __launch_bounds__(256) agg64_kernel(const float* __restrict__ t,
                                                    const int* __restrict__ csr,
                                                    const int* __restrict__ off,
                                                    const int* __restrict__ deg,
                                                    const float* __restrict__ b,
                                                    float* __restrict__ out, int n) {
    int gw   = (blockIdx.x * blockDim.x + threadIdx.x) >> 5;
    int lane = threadIdx.x & 31;
    if (gw >= n) return;
    int half = lane >> 4;
    int sub  = lane & 15;
    int o  = __ldg(&off[gw]);
    int dg = __ldg(&deg[gw]);
    int e  = o + dg;
    float4 acc = make_float4(0.f, 0.f, 0.f, 0.f);
    int i = o;
    for (; i + 3 < e; i += 4) {
        int s0 = __ldg(&csr[i + half]);
        int s1 = __ldg(&csr[i + 2 + half]);
        float4 v0 = __ldg((const float4*)(t + (size_t)s0 * 64) + sub);
        float4 v1 = __ldg((const float4*)(t + (size_t)s1 * 64) + sub);
        acc.x += v0.x + v1.x; acc.y += v0.y + v1.y;
        acc.z += v0.z + v1.z; acc.w += v0.w + v1.w;
    }
    for (; i + 1 < e; i += 2) {
        int s = __ldg(&csr[i + half]);
        float4 v = __ldg((const float4*)(t + (size_t)s * 64) + sub);
        acc.x += v.x; acc.y += v.y; acc.z += v.z; acc.w += v.w;
    }
    if (i < e && half == 0) {
        int s = __ldg(&csr[i]);
        float4 v = __ldg((const float4*)(t + (size_t)s * 64) + sub);
        acc.x += v.x; acc.y += v.y; acc.z += v.z; acc.w += v.w;
    }
    // combine the two edge slots
    acc.x += __shfl_xor_sync(0xffffffffu, acc.x, 16);
    acc.y += __shfl_xor_sync(0xffffffffu, acc.y, 16);
    acc.z += __shfl_xor_sync(0xffffffffu, acc.z, 16);
    acc.w += __shfl_xor_sync(0xffffffffu, acc.w, 16);
    if (half == 0) {
        float inv = 1.0f / fmaxf((float)dg, 1.0f);
        float4 bb = __ldg((const float4*)b + sub);
        ((float4*)(out + (size_t)gw * 64))[sub] =
            make_float4(acc.x * inv + bb.x, acc.y * inv + bb.y,
                        acc.z * inv + bb.z, acc.w * inv + bb.w);
    }
}

__global__ void __launch_bounds__(256) agg64_dual_kernel(
        const float* __restrict__ tA, const int* __restrict__ csrA,
        const int* __restrict__ offA, const int* __restrict__ degA,
        const float* __restrict__ bA,
        const float* __restrict__ tB, const int* __restrict__ csrB,
        const int* __restrict__ offB, const int* __restrict__ degB,
        const float* __restrict__ bB,
        float* __restrict__ out, int n) {
    int gw   = (blockIdx.x * blockDim.x + threadIdx.x) >> 5;
    int lane = threadIdx.x & 31;
    if (gw >= n) return;
    int half = lane >> 4;
    int sub  = lane & 15;

    int dgA = __ldg(&degA[gw]);
    int dgB = __ldg(&degB[gw]);

    float4 accA = make_float4(0.f, 0.f, 0.f, 0.f);
    {
        int o = __ldg(&offA[gw]); int e = o + dgA;
        int i = o;
        for (; i + 3 < e; i += 4) {
            int s0 = __ldg(&csrA[i + half]);
            int s1 = __ldg(&csrA[i + 2 + half]);
            float4 v0 = __ldg((const float4*)(tA + (size_t)s0 * 64) + sub);
            float4 v1 = __ldg((const float4*)(tA + (size_t)s1 * 64) + sub);
            accA.x += v0.x + v1.x; accA.y += v0.y + v1.y;
            accA.z += v0.z + v1.z; accA.w += v0.w + v1.w;
        }
        for (; i + 1 < e; i += 2) {
            int s = __ldg(&csrA[i + half]);
            float4 v = __ldg((const float4*)(tA + (size_t)s * 64) + sub);
            accA.x += v.x; accA.y += v.y; accA.z += v.z; accA.w += v.w;
        }
        if (i < e && half == 0) {
            int s = __ldg(&csrA[i]);
            float4 v = __ldg((const float4*)(tA + (size_t)s * 64) + sub);
            accA.x += v.x; accA.y += v.y; accA.z += v.z; accA.w += v.w;
        }
    }
    float4 accB = make_float4(0.f, 0.f, 0.f, 0.f);
    {
        int o = __ldg(&offB[gw]); int e = o + dgB;
        int i = o;
        for (; i + 3 < e; i += 4) {
            int s0 = __ldg(&csrB[i + half]);
            int s1 = __ldg(&csrB[i + 2 + half]);
            float4 v0 = __ldg((const float4*)(tB + (size_t)s0 * 64) + sub);
            float4 v1 = __ldg((const float4*)(tB + (size_t)s1 * 64) + sub);
            accB.x += v0.x + v1.x; accB.y += v0.y + v1.y;
            accB.z += v0.z + v1.z; accB.w += v0.w + v1.w;
        }
        for (; i + 1 < e; i += 2) {
            int s = __ldg(&csrB[i + half]);
            float4 v = __ldg((const float4*)(tB + (size_t)s * 64) + sub);
            accB.x += v.x; accB.y += v.y; accB.z += v.z; accB.w += v.w;
        }
        if (i < e && half == 0) {
            int s = __ldg(&csrB[i]);
            float4 v = __ldg((const float4*)(tB + (size_t)s * 64) + sub);
            accB.x += v.x; accB.y += v.y; accB.z += v.z; accB.w += v.w;
        }
    }
    accA.x += __shfl_xor_sync(0xffffffffu, accA.x, 16);
    accA.y += __shfl_xor_sync(0xffffffffu, accA.y, 16);
    accA.z += __shfl_xor_sync(0xffffffffu, accA.z, 16);
    accA.w += __shfl_xor_sync(0xffffffffu, accA.w, 16);
    accB.x += __shfl_xor_sync(0xffffffffu, accB.x, 16);
    accB.y += __shfl_xor_sync(0xffffffffu, accB.y, 16);
    accB.z += __shfl_xor_sync(0xffffffffu, accB.z, 16);
    accB.w += __shfl_xor_sync(0xffffffffu, accB.w, 16);
    if (half == 0) {
        float invA = 1.0f / fmaxf((float)dgA, 1.0f);
        float invB = 1.0f / fmaxf((float)dgB, 1.0f);
        float4 bbA = __ldg((const float4*)bA + sub);
        float4 bbB = __ldg((const float4*)bB + sub);
        ((float4*)(out + (size_t)gw * 64))[sub] =
            make_float4(accA.x * invA + bbA.x + accB.x * invB + bbB.x,
                        accA.y * invA + bbA.y + accB.y * invB + bbB.y,
                        accA.z * invA + bbA.z + accB.z * invB + bbB.z,
                        accA.w * invA + bbA.w + accB.w * invB + bbB.w);
    }
}

// ---------------- launch ----------------

extern "C" void kernel_launch(void* const* d_in, const int* in_sizes, int n_in,
                              void* d_out, int out_size) {
    const float* x_drug = (const float*)d_in[0];
    const float* x_prot = (const float*)d_in[1];
    const int* src_ddi  = (const int*)d_in[2];
    const int* dst_ddi  = (const int*)d_in[3];
    const int* src_dpi  = (const int*)d_in[4];
    const int* dst_dpi  = (const int*)d_in[5];
    const int* src_ppi  = (const int*)d_in[6];
    const int* dst_ppi  = (const int*)d_in[7];
    const float* W1_ddi = (const float*)d_in[8];
    const float* b1_ddi = (const float*)d_in[9];
    const float* W1_dpi = (const float*)d_in[10];
    const float* b1_dpi = (const float*)d_in[11];
    const float* W1_ppi = (const float*)d_in[12];
    const float* b1_ppi = (const float*)d_in[13];
    const float* W2_ddi = (const float*)d_in[14];
    const float* b2_ddi = (const float*)d_in[15];
    const float* W2_dpi = (const float*)d_in[16];
    const float* b2_dpi = (const float*)d_in[17];
    const float* W2_ppi = (const float*)d_in[18];
    const float* b2_ppi = (const float*)d_in[19];
    float* out = (float*)d_out;

    float* B = nullptr;
    cudaGetSymbolAddress((void**)&B, g_buf);
    int* IB = nullptr;
    cudaGetSymbolAddress((void**)&IB, g_ibuf);

    float* h_d    = B + H_D;
    float* h_p    = B + H_P;
    float* t1_ddi = B + T1_DDI;
    float* t1_dpi = B + T1_DPI;
    float* t1_ppi = B + T1_PPI;
    float* t2_ddi = B + T2_DDI;
    float* t2_dpi = B + T2_DPI;
    float* t2_ppi = B + T2_PPI;

    int* deg_ddi = IB + DEG0;
    int* deg_dpi = IB + DEG0 + NN;
    int* deg_ppi = IB + DEG0 + 2 * NN;
    int* off_ddi = IB + OFF0;
    int* off_dpi = IB + OFF0 + NN;
    int* off_ppi = IB + OFF0 + 2 * NN;
    int* cur_ddi = IB + CUR0;
    int* cur_dpi = IB + CUR0 + NN;
    int* cur_ppi = IB + CUR0 + 2 * NN;
    int* csr_ddi = IB + CSR0;
    int* csr_dpi = IB + CSR0 + EE;
    int* csr_ppi = IB + CSR0 + 2 * EE;

    // ---- build CSR (3 relations) ----
    zero_int_kernel<<<64, 1024>>>(IB + DEG0, 3 * NN);
    degree_kernel<<<(EE + 255) / 256, 256>>>(dst_ddi, dst_dpi, dst_ppi,
                                             deg_ddi, deg_dpi, deg_ppi);
    scan3_kernel<<<3, 1024>>>(IB);
    fill_csr3_kernel<<<(3 * EE + 255) / 256, 256>>>(
        src_ddi, dst_ddi, cur_ddi, csr_ddi,
        src_dpi, dst_dpi, cur_dpi, csr_dpi,
        src_ppi, dst_ppi, cur_ppi, csr_ppi);

    // ---- layer 1 ----
    const int GB = (NN + 63) / 64;
    gemm_dual_kernel<128, 16><<<GB, 256>>>(x_drug, W1_ddi, W1_dpi, t1_ddi, t1_dpi, ND);
    gemm_kernel<128><<<GB, 256>>>(x_prot, W1_ppi, t1_ppi, NP);

    const int AB = (NN * 32 + 255) / 256;
    agg128_kernel<<<AB, 256>>>(t1_ddi, csr_ddi, off_ddi, deg_ddi, b1_ddi, h_d, ND);
    agg128_dual_kernel<<<AB, 256>>>(t1_dpi, csr_dpi, off_dpi, deg_dpi, b1_dpi,
                                    t1_ppi, csr_ppi, off_ppi, deg_ppi, b1_ppi,
                                    h_p, NP);

    // ---- layer 2 ----
    gemm_dual_kernel<64, 32><<<GB, 256>>>(h_d, W2_ddi, W2_dpi, t2_ddi, t2_dpi, ND);
    gemm_kernel<64><<<GB, 256>>>(h_p, W2_ppi, t2_ppi, NP);

    agg64_kernel<<<AB, 256>>>(t2_ddi, csr_ddi, off_ddi, deg_ddi, b2_ddi, out, ND);
    agg64_dual_kernel<<<AB, 256>>>(t2_dpi, csr_dpi, off_dpi, deg_dpi, b2_dpi,
                                   t2_ppi, csr_ppi, off_ppi, deg_ppi, b2_ppi,
                                   out + (size_t)ND * DO, NP);
}